// round 2
// baseline (speedup 1.0000x reference)
#include <cuda_runtime.h>
#include <cuda_fp16.h>
#include <cstdint>

#define TOK   4096
#define HID   2048
#define INTER 5632

#define BM 128
#define BN 64
#define BK 32
#define SSTR 56   // smem row stride in halves: 112B (16B aligned), 28 words -> conflict-free frags

// ---- scratch (device globals; no runtime allocation allowed) ----
__device__ __half g_xh[(size_t)TOK * HID];      // x in fp16
__device__ __half g_wg[(size_t)INTER * HID];    // gate_w fp16
__device__ __half g_wu[(size_t)INTER * HID];    // up_w fp16
__device__ __half g_wd[(size_t)HID * INTER];    // down_w fp16
__device__ __half g_hbuf[(size_t)TOK * INTER];  // hidden activation fp16

// ---- fp32 -> fp16 conversion, vectorized ----
__global__ void convert_f2h(const float* __restrict__ in, __half* __restrict__ out, int n4) {
  int i = blockIdx.x * blockDim.x + threadIdx.x;
  int stride = gridDim.x * blockDim.x;
  for (; i < n4; i += stride) {
    float4 v = reinterpret_cast<const float4*>(in)[i];
    __half2 h0 = __floats2half2_rn(v.x, v.y);
    __half2 h1 = __floats2half2_rn(v.z, v.w);
    reinterpret_cast<__half2*>(out)[2 * i]     = h0;
    reinterpret_cast<__half2*>(out)[2 * i + 1] = h1;
  }
}

__device__ __forceinline__ void mma16816(float* c, const uint32_t* a, const uint32_t* b) {
  asm volatile(
      "mma.sync.aligned.m16n8k16.row.col.f32.f16.f16.f32 "
      "{%0,%1,%2,%3}, {%4,%5,%6,%7}, {%8,%9}, {%0,%1,%2,%3};\n"
      : "+f"(c[0]), "+f"(c[1]), "+f"(c[2]), "+f"(c[3])
      : "r"(a[0]), "r"(a[1]), "r"(a[2]), "r"(a[3]), "r"(b[0]), "r"(b[1]));
}

// =====================================================================
// GEMM1 (fused gate+up): h[t,i] = silu(x@Wg^T * gs) * (x@Wu^T * us), fp16 out
// A = g_xh [TOK,HID], B = Wg/Wu [INTER,HID] (K contiguous -> mma row.col)
// CTA: 128(M) x 64(N), BK=32, 8 warps (4x2) of 32x32
// =====================================================================
__global__ __launch_bounds__(256, 1)
void gemm1_kernel(const __half* __restrict__ X,
                  const __half* __restrict__ Wg,
                  const __half* __restrict__ Wu,
                  const float* __restrict__ gs,
                  const float* __restrict__ us,
                  __half* __restrict__ Hout) {
  __shared__ __half As[BM * SSTR];
  __shared__ __half Bgs[BN * SSTR];
  __shared__ __half Bus[BN * SSTR];

  const int tid  = threadIdx.x;
  const int lane = tid & 31;
  const int warp = tid >> 5;
  const int wm   = warp & 3;   // 0..3 -> m offset wm*32
  const int wn   = warp >> 2;  // 0..1 -> n offset wn*32
  const int g    = lane >> 2;  // 0..7
  const int t    = lane & 3;   // 0..3

  const int mBase = blockIdx.y * BM;
  const int nBase = blockIdx.x * BN;

  // global -> smem mapping (coalesced 16B chunks)
  const int kc    = tid & 3;        // which 8-half chunk in the 32-wide K tile
  const int arow0 = tid >> 2;       // 0..63
  const int arow1 = arow0 + 64;
  const int brow  = tid >> 2;       // 0..63

  const __half* Ag0 = X  + (size_t)(mBase + arow0) * HID + kc * 8;
  const __half* Ag1 = X  + (size_t)(mBase + arow1) * HID + kc * 8;
  const __half* Bgg = Wg + (size_t)(nBase + brow)  * HID + kc * 8;
  const __half* Bug = Wu + (size_t)(nBase + brow)  * HID + kc * 8;

  uint4* sA0 = reinterpret_cast<uint4*>(As  + arow0 * SSTR + kc * 8);
  uint4* sA1 = reinterpret_cast<uint4*>(As  + arow1 * SSTR + kc * 8);
  uint4* sBg = reinterpret_cast<uint4*>(Bgs + brow  * SSTR + kc * 8);
  uint4* sBu = reinterpret_cast<uint4*>(Bus + brow  * SSTR + kc * 8);

  float accg[2][4][4];
  float accu[2][4][4];
#pragma unroll
  for (int i = 0; i < 2; i++)
#pragma unroll
    for (int j = 0; j < 4; j++)
#pragma unroll
      for (int k = 0; k < 4; k++) { accg[i][j][k] = 0.f; accu[i][j][k] = 0.f; }

  // prologue: tile 0
  uint4 ra0 = *reinterpret_cast<const uint4*>(Ag0);
  uint4 ra1 = *reinterpret_cast<const uint4*>(Ag1);
  uint4 rbg = *reinterpret_cast<const uint4*>(Bgg);
  uint4 rbu = *reinterpret_cast<const uint4*>(Bug);
  *sA0 = ra0; *sA1 = ra1; *sBg = rbg; *sBu = rbu;

  const int KT = HID / BK;  // 64
  for (int kt = 0; kt < KT; kt++) {
    __syncthreads();
    if (kt + 1 < KT) {
      const int off = (kt + 1) * BK;
      ra0 = *reinterpret_cast<const uint4*>(Ag0 + off);
      ra1 = *reinterpret_cast<const uint4*>(Ag1 + off);
      rbg = *reinterpret_cast<const uint4*>(Bgg + off);
      rbu = *reinterpret_cast<const uint4*>(Bug + off);
    }
#pragma unroll
    for (int ks = 0; ks < 2; ks++) {
      const int k0 = ks * 16;
      uint32_t a[2][4];
#pragma unroll
      for (int mt = 0; mt < 2; mt++) {
        const __half* p = As + (wm * 32 + mt * 16) * SSTR + k0;
        a[mt][0] = *reinterpret_cast<const uint32_t*>(p + g * SSTR + 2 * t);
        a[mt][1] = *reinterpret_cast<const uint32_t*>(p + (g + 8) * SSTR + 2 * t);
        a[mt][2] = *reinterpret_cast<const uint32_t*>(p + g * SSTR + 2 * t + 8);
        a[mt][3] = *reinterpret_cast<const uint32_t*>(p + (g + 8) * SSTR + 2 * t + 8);
      }
      uint32_t bgf[4][2], buf2[4][2];
#pragma unroll
      for (int nt = 0; nt < 4; nt++) {
        const __half* p = Bgs + (wn * 32 + nt * 8 + g) * SSTR + k0 + 2 * t;
        bgf[nt][0] = *reinterpret_cast<const uint32_t*>(p);
        bgf[nt][1] = *reinterpret_cast<const uint32_t*>(p + 8);
        const __half* q = Bus + (wn * 32 + nt * 8 + g) * SSTR + k0 + 2 * t;
        buf2[nt][0] = *reinterpret_cast<const uint32_t*>(q);
        buf2[nt][1] = *reinterpret_cast<const uint32_t*>(q + 8);
      }
#pragma unroll
      for (int mt = 0; mt < 2; mt++)
#pragma unroll
        for (int nt = 0; nt < 4; nt++) {
          mma16816(accg[mt][nt], a[mt], bgf[nt]);
          mma16816(accu[mt][nt], a[mt], buf2[nt]);
        }
    }
    __syncthreads();
    if (kt + 1 < KT) { *sA0 = ra0; *sA1 = ra1; *sBg = rbg; *sBu = rbu; }
  }

  // epilogue: dequant, silu-gate, write fp16 h
  const int r0 = mBase + wm * 32;
  const int c0 = nBase + wn * 32;
#pragma unroll
  for (int mt = 0; mt < 2; mt++) {
#pragma unroll
    for (int nt = 0; nt < 4; nt++) {
      const int c = c0 + nt * 8 + 2 * t;
      const float gs0 = gs[c], gs1 = gs[c + 1];
      const float us0 = us[c], us1 = us[c + 1];
      const float* cg = accg[mt][nt];
      const float* cu = accu[mt][nt];
      const int r = r0 + mt * 16 + g;

      float g00 = cg[0] * gs0, g01 = cg[1] * gs1;
      float g10 = cg[2] * gs0, g11 = cg[3] * gs1;
      float u00 = cu[0] * us0, u01 = cu[1] * us1;
      float u10 = cu[2] * us0, u11 = cu[3] * us1;

      float h00 = g00 / (1.f + expf(-g00)) * u00;
      float h01 = g01 / (1.f + expf(-g01)) * u01;
      float h10 = g10 / (1.f + expf(-g10)) * u10;
      float h11 = g11 / (1.f + expf(-g11)) * u11;

      *reinterpret_cast<__half2*>(Hout + (size_t)r * INTER + c) =
          __floats2half2_rn(h00, h01);
      *reinterpret_cast<__half2*>(Hout + (size_t)(r + 8) * INTER + c) =
          __floats2half2_rn(h10, h11);
    }
  }
}

// =====================================================================
// GEMM2: out[t,h] = (hbuf @ Wd^T) * ds, fp32 out
// A = g_hbuf [TOK,INTER], B = Wd [HID,INTER] (K contiguous)
// =====================================================================
__global__ __launch_bounds__(256, 1)
void gemm2_kernel(const __half* __restrict__ A,
                  const __half* __restrict__ B,
                  const float* __restrict__ ds,
                  float* __restrict__ Out) {
  __shared__ __half As[BM * SSTR];
  __shared__ __half Bs[BN * SSTR];

  const int tid  = threadIdx.x;
  const int lane = tid & 31;
  const int warp = tid >> 5;
  const int wm   = warp & 3;
  const int wn   = warp >> 2;
  const int g    = lane >> 2;
  const int t    = lane & 3;

  const int mBase = blockIdx.y * BM;
  const int nBase = blockIdx.x * BN;

  const int kc    = tid & 3;
  const int arow0 = tid >> 2;
  const int arow1 = arow0 + 64;
  const int brow  = tid >> 2;

  const __half* Ag0 = A + (size_t)(mBase + arow0) * INTER + kc * 8;
  const __half* Ag1 = A + (size_t)(mBase + arow1) * INTER + kc * 8;
  const __half* Bgp = B + (size_t)(nBase + brow)  * INTER + kc * 8;

  uint4* sA0 = reinterpret_cast<uint4*>(As + arow0 * SSTR + kc * 8);
  uint4* sA1 = reinterpret_cast<uint4*>(As + arow1 * SSTR + kc * 8);
  uint4* sB  = reinterpret_cast<uint4*>(Bs + brow  * SSTR + kc * 8);

  float acc[2][4][4];
#pragma unroll
  for (int i = 0; i < 2; i++)
#pragma unroll
    for (int j = 0; j < 4; j++)
#pragma unroll
      for (int k = 0; k < 4; k++) acc[i][j][k] = 0.f;

  uint4 ra0 = *reinterpret_cast<const uint4*>(Ag0);
  uint4 ra1 = *reinterpret_cast<const uint4*>(Ag1);
  uint4 rb  = *reinterpret_cast<const uint4*>(Bgp);
  *sA0 = ra0; *sA1 = ra1; *sB = rb;

  const int KT = INTER / BK;  // 176
  for (int kt = 0; kt < KT; kt++) {
    __syncthreads();
    if (kt + 1 < KT) {
      const int off = (kt + 1) * BK;
      ra0 = *reinterpret_cast<const uint4*>(Ag0 + off);
      ra1 = *reinterpret_cast<const uint4*>(Ag1 + off);
      rb  = *reinterpret_cast<const uint4*>(Bgp + off);
    }
#pragma unroll
    for (int ks = 0; ks < 2; ks++) {
      const int k0 = ks * 16;
      uint32_t a[2][4];
#pragma unroll
      for (int mt = 0; mt < 2; mt++) {
        const __half* p = As + (wm * 32 + mt * 16) * SSTR + k0;
        a[mt][0] = *reinterpret_cast<const uint32_t*>(p + g * SSTR + 2 * t);
        a[mt][1] = *reinterpret_cast<const uint32_t*>(p + (g + 8) * SSTR + 2 * t);
        a[mt][2] = *reinterpret_cast<const uint32_t*>(p + g * SSTR + 2 * t + 8);
        a[mt][3] = *reinterpret_cast<const uint32_t*>(p + (g + 8) * SSTR + 2 * t + 8);
      }
      uint32_t bf[4][2];
#pragma unroll
      for (int nt = 0; nt < 4; nt++) {
        const __half* p = Bs + (wn * 32 + nt * 8 + g) * SSTR + k0 + 2 * t;
        bf[nt][0] = *reinterpret_cast<const uint32_t*>(p);
        bf[nt][1] = *reinterpret_cast<const uint32_t*>(p + 8);
      }
#pragma unroll
      for (int mt = 0; mt < 2; mt++)
#pragma unroll
        for (int nt = 0; nt < 4; nt++)
          mma16816(acc[mt][nt], a[mt], bf[nt]);
    }
    __syncthreads();
    if (kt + 1 < KT) { *sA0 = ra0; *sA1 = ra1; *sB = rb; }
  }

  const int r0 = mBase + wm * 32;
  const int c0 = nBase + wn * 32;
#pragma unroll
  for (int mt = 0; mt < 2; mt++) {
#pragma unroll
    for (int nt = 0; nt < 4; nt++) {
      const int c = c0 + nt * 8 + 2 * t;
      const float d0 = ds[c], d1 = ds[c + 1];
      const float* cc = acc[mt][nt];
      const int r = r0 + mt * 16 + g;
      float2 v0 = make_float2(cc[0] * d0, cc[1] * d1);
      float2 v1 = make_float2(cc[2] * d0, cc[3] * d1);
      *reinterpret_cast<float2*>(Out + (size_t)r * HID + c) = v0;
      *reinterpret_cast<float2*>(Out + (size_t)(r + 8) * HID + c) = v1;
    }
  }
}

// =====================================================================
extern "C" void kernel_launch(void* const* d_in, const int* in_sizes, int n_in,
                              void* d_out, int out_size) {
  const float* x      = (const float*)d_in[0];
  const float* gate_w = (const float*)d_in[1];
  const float* up_w   = (const float*)d_in[2];
  const float* down_w = (const float*)d_in[3];
  const float* gate_s = (const float*)d_in[4];
  const float* up_s   = (const float*)d_in[5];
  const float* down_s = (const float*)d_in[6];
  float* out = (float*)d_out;

  __half *xh, *wg, *wu, *wd, *hb;
  cudaGetSymbolAddress((void**)&xh, g_xh);
  cudaGetSymbolAddress((void**)&wg, g_wg);
  cudaGetSymbolAddress((void**)&wu, g_wu);
  cudaGetSymbolAddress((void**)&wd, g_wd);
  cudaGetSymbolAddress((void**)&hb, g_hbuf);

  const int n4x = (TOK * HID) / 4;        // 2,097,152
  const int n4w = (INTER * HID) / 4;      // 2,883,584

  convert_f2h<<<2048, 256>>>(x, xh, n4x);
  convert_f2h<<<2048, 256>>>(gate_w, wg, n4w);
  convert_f2h<<<2048, 256>>>(up_w, wu, n4w);
  convert_f2h<<<2048, 256>>>(down_w, wd, n4w);

  dim3 grid1(INTER / BN, TOK / BM);  // (88, 32)
  gemm1_kernel<<<grid1, 256>>>(xh, wg, wu, gate_s, up_s, hb);

  dim3 grid2(HID / BN, TOK / BM);    // (32, 32)
  gemm2_kernel<<<grid2, 256>>>(hb, wd, down_s, out);
}

// round 4
// speedup vs baseline: 1.9582x; 1.9582x over previous
#include <cuda_runtime.h>
#include <cuda_fp16.h>
#include <cstdint>

#define TOK   4096
#define HID   2048
#define INTER 5632

// ---- scratch (device globals; no runtime allocation allowed) ----
__device__ __half g_xh[(size_t)TOK * HID];      // x in fp16
__device__ __half g_wg[(size_t)INTER * HID];    // gate_w fp16
__device__ __half g_wu[(size_t)INTER * HID];    // up_w fp16
__device__ __half g_wd[(size_t)HID * INTER];    // down_w fp16
__device__ __half g_hbuf[(size_t)TOK * INTER];  // hidden activation fp16

// ---- fp32 -> fp16 conversion, vectorized ----
__global__ void convert_f2h(const float* __restrict__ in, __half* __restrict__ out, int n4) {
  int i = blockIdx.x * blockDim.x + threadIdx.x;
  int stride = gridDim.x * blockDim.x;
  for (; i < n4; i += stride) {
    float4 v = reinterpret_cast<const float4*>(in)[i];
    __half2 h0 = __floats2half2_rn(v.x, v.y);
    __half2 h1 = __floats2half2_rn(v.z, v.w);
    reinterpret_cast<__half2*>(out)[2 * i]     = h0;
    reinterpret_cast<__half2*>(out)[2 * i + 1] = h1;
  }
}

// =====================================================================
// helpers: mma.sync / ldmatrix / cp.async  (all valid on plain sm_103)
// =====================================================================
__device__ __forceinline__ uint32_t smem_u32(const void* p) {
  uint32_t a;
  asm("{ .reg .u64 t; cvta.to.shared.u64 t, %1; cvt.u32.u64 %0, t; }" : "=r"(a) : "l"(p));
  return a;
}

__device__ __forceinline__ void mma16816(float* c, const uint32_t* a, const uint32_t* b) {
  asm volatile(
      "mma.sync.aligned.m16n8k16.row.col.f32.f16.f16.f32 "
      "{%0,%1,%2,%3}, {%4,%5,%6,%7}, {%8,%9}, {%0,%1,%2,%3};\n"
      : "+f"(c[0]), "+f"(c[1]), "+f"(c[2]), "+f"(c[3])
      : "r"(a[0]), "r"(a[1]), "r"(a[2]), "r"(a[3]), "r"(b[0]), "r"(b[1]));
}

__device__ __forceinline__ void ldsm4(uint32_t* r, uint32_t addr) {
  asm volatile("ldmatrix.sync.aligned.m8n8.x4.shared.b16 {%0,%1,%2,%3}, [%4];"
               : "=r"(r[0]), "=r"(r[1]), "=r"(r[2]), "=r"(r[3]) : "r"(addr));
}

__device__ __forceinline__ void cp16(uint32_t s, const void* g) {
  asm volatile("cp.async.cg.shared.global [%0], [%1], 16;" :: "r"(s), "l"(g));
}
#define CP_COMMIT() asm volatile("cp.async.commit_group;" ::: "memory")

// Tile geometry: BK = 64 halves = 128 bytes per row -> canonical SW128 swizzle.
// smem byte offset of (row, 16B-chunk c):  row*128 + ((c ^ (row&7)) << 4)

// =====================================================================
// GEMM1 fused gate+up: h = silu(X@Wg^T * gs) * (X@Wu^T * us), fp16 out
// CTA tile: M=128 x N=64 (per weight matrix), BK=64, 2-stage cp.async.
// 8 warps: wm=warp&3 (32 rows), wn=warp>>2 (32 cols); acc 32x32 per matrix.
// smem: stage s at s*32768: A(16KB) | Bg(8KB) | Bu(8KB)
// =====================================================================
__global__ __launch_bounds__(256, 2)
void gemm1_mma(const __half* __restrict__ X, const __half* __restrict__ Wg,
               const __half* __restrict__ Wu, const float* __restrict__ gs,
               const float* __restrict__ us, __half* __restrict__ Hout) {
  extern __shared__ char smem[];
  const uint32_t sb = smem_u32(smem);
  const int tid = threadIdx.x, lane = tid & 31, warp = tid >> 5;
  const int wm = warp & 3, wn = warp >> 2;       // wn in {0,1}
  const int mBase = blockIdx.y * 128;
  const int nBase = blockIdx.x * 64;
  const int s7 = lane & 7;

  // per-lane fragment base offsets (bytes within tile)
  const uint32_t aRow = (uint32_t)((wm * 32 + (lane & 15)) * 128);
  const int hiA = lane >> 4;                      // 16B chunk parity for A
  const uint32_t bRow = (uint32_t)((wn * 32 + (lane & 7) + ((lane >> 4) & 1) * 8) * 128);
  const int cB = (lane >> 3) & 1;                 // 16B chunk parity for B

  float ag[2][4][4], au[2][4][4];
#pragma unroll
  for (int i = 0; i < 2; i++)
#pragma unroll
    for (int j = 0; j < 4; j++)
#pragma unroll
      for (int k = 0; k < 4; k++) { ag[i][j][k] = 0.f; au[i][j][k] = 0.f; }

  auto load_stage = [&](int kt, int b) {
    const uint32_t base = sb + (uint32_t)b * 32768u;
    const int k0 = kt * 64;
#pragma unroll
    for (int i = 0; i < 4; i++) {               // A: 1024 chunks / 256 thr
      int ch = tid + i * 256;
      int row = ch >> 3, c = ch & 7;
      uint32_t sw = (uint32_t)(row * 128 + ((c ^ (row & 7)) << 4));
      cp16(base + sw, X + (size_t)(mBase + row) * HID + k0 + c * 8);
    }
#pragma unroll
    for (int i = 0; i < 2; i++) {               // Bg,Bu: 512 chunks each
      int ch = tid + i * 256;
      int row = ch >> 3, c = ch & 7;
      uint32_t sw = (uint32_t)(row * 128 + ((c ^ (row & 7)) << 4));
      cp16(base + 16384u + sw, Wg + (size_t)(nBase + row) * HID + k0 + c * 8);
      cp16(base + 24576u + sw, Wu + (size_t)(nBase + row) * HID + k0 + c * 8);
    }
    CP_COMMIT();
  };

  const int KT = HID / 64;  // 32
  load_stage(0, 0);
  load_stage(1, 1);

  for (int kt = 0; kt < KT; kt++) {
    const int b = kt & 1;
    if (kt + 1 < KT) asm volatile("cp.async.wait_group 1;" ::: "memory");
    else             asm volatile("cp.async.wait_group 0;" ::: "memory");
    __syncthreads();

    const uint32_t base = sb + (uint32_t)b * 32768u;
    const uint32_t aB = base + aRow;
    const uint32_t gB = base + 16384u + bRow;
    const uint32_t uB = base + 24576u + bRow;
#pragma unroll
    for (int kk = 0; kk < 4; kk++) {
      const uint32_t aOff = (uint32_t)((((kk * 2 + hiA) ^ s7)) << 4);
      uint32_t a[2][4];
      ldsm4(a[0], aB + aOff);
      ldsm4(a[1], aB + 2048u + aOff);
      const uint32_t bOff = (uint32_t)((((kk * 2 + cB) ^ s7)) << 4);
      uint32_t bg[2][4], bu[2][4];
#pragma unroll
      for (int np = 0; np < 2; np++) {
        ldsm4(bg[np], gB + (uint32_t)(np * 2048) + bOff);
        ldsm4(bu[np], uB + (uint32_t)(np * 2048) + bOff);
      }
#pragma unroll
      for (int mt = 0; mt < 2; mt++)
#pragma unroll
        for (int np = 0; np < 2; np++) {
          mma16816(ag[mt][np * 2 + 0], a[mt], &bg[np][0]);
          mma16816(ag[mt][np * 2 + 1], a[mt], &bg[np][2]);
          mma16816(au[mt][np * 2 + 0], a[mt], &bu[np][0]);
          mma16816(au[mt][np * 2 + 1], a[mt], &bu[np][2]);
        }
    }
    __syncthreads();
    if (kt + 2 < KT) load_stage(kt + 2, b);
  }

  // epilogue: dequant + silu-gate, fp16 out
  const int g = lane >> 2, t = lane & 3;
#pragma unroll
  for (int mt = 0; mt < 2; mt++) {
#pragma unroll
    for (int n8 = 0; n8 < 4; n8++) {
      // acc index n8 = np*2+sub -> cols np*16 + sub*8
      const int col = nBase + wn * 32 + (n8 >> 1) * 16 + (n8 & 1) * 8 + 2 * t;
      const float gs0 = __ldg(gs + col), gs1 = __ldg(gs + col + 1);
      const float us0 = __ldg(us + col), us1 = __ldg(us + col + 1);
      const float* cg = ag[mt][n8];
      const float* cu = au[mt][n8];
      const int r = mBase + wm * 32 + mt * 16 + g;

      float g00 = cg[0] * gs0, g01 = cg[1] * gs1;
      float g10 = cg[2] * gs0, g11 = cg[3] * gs1;
      float u00 = cu[0] * us0, u01 = cu[1] * us1;
      float u10 = cu[2] * us0, u11 = cu[3] * us1;

      float h00 = g00 / (1.f + expf(-g00)) * u00;
      float h01 = g01 / (1.f + expf(-g01)) * u01;
      float h10 = g10 / (1.f + expf(-g10)) * u10;
      float h11 = g11 / (1.f + expf(-g11)) * u11;

      *reinterpret_cast<__half2*>(Hout + (size_t)r * INTER + col) =
          __floats2half2_rn(h00, h01);
      *reinterpret_cast<__half2*>(Hout + (size_t)(r + 8) * INTER + col) =
          __floats2half2_rn(h10, h11);
    }
  }
}

// =====================================================================
// GEMM2: out = (H @ Wd^T) * ds, fp32 out. CTA tile M=128 x N=128, BK=64.
// 8 warps: wm=warp&3 (32 rows), wn=warp>>2 (64 cols); warp 32x64.
// smem: stage s at s*32768: A(16KB) | B(16KB)
// =====================================================================
__global__ __launch_bounds__(256, 2)
void gemm2_mma(const __half* __restrict__ H, const __half* __restrict__ Wd,
               const float* __restrict__ ds, float* __restrict__ Out) {
  extern __shared__ char smem[];
  const uint32_t sb = smem_u32(smem);
  const int tid = threadIdx.x, lane = tid & 31, warp = tid >> 5;
  const int wm = warp & 3, wn = warp >> 2;       // wn in {0,1}
  const int mBase = blockIdx.y * 128;
  const int nBase = blockIdx.x * 128;
  const int s7 = lane & 7;

  const uint32_t aRow = (uint32_t)((wm * 32 + (lane & 15)) * 128);
  const int hiA = lane >> 4;
  const uint32_t bRow = (uint32_t)((wn * 64 + (lane & 7) + ((lane >> 4) & 1) * 8) * 128);
  const int cB = (lane >> 3) & 1;

  float acc[2][8][4];
#pragma unroll
  for (int i = 0; i < 2; i++)
#pragma unroll
    for (int j = 0; j < 8; j++)
#pragma unroll
      for (int k = 0; k < 4; k++) acc[i][j][k] = 0.f;

  auto load_stage = [&](int kt, int b) {
    const uint32_t base = sb + (uint32_t)b * 32768u;
    const int k0 = kt * 64;
#pragma unroll
    for (int i = 0; i < 4; i++) {
      int ch = tid + i * 256;
      int row = ch >> 3, c = ch & 7;
      uint32_t sw = (uint32_t)(row * 128 + ((c ^ (row & 7)) << 4));
      cp16(base + sw,          H  + (size_t)(mBase + row) * INTER + k0 + c * 8);
      cp16(base + 16384u + sw, Wd + (size_t)(nBase + row) * INTER + k0 + c * 8);
    }
    CP_COMMIT();
  };

  const int KT = INTER / 64;  // 88
  load_stage(0, 0);
  load_stage(1, 1);

  for (int kt = 0; kt < KT; kt++) {
    const int b = kt & 1;
    if (kt + 1 < KT) asm volatile("cp.async.wait_group 1;" ::: "memory");
    else             asm volatile("cp.async.wait_group 0;" ::: "memory");
    __syncthreads();

    const uint32_t base = sb + (uint32_t)b * 32768u;
    const uint32_t aB = base + aRow;
    const uint32_t bB = base + 16384u + bRow;
#pragma unroll
    for (int kk = 0; kk < 4; kk++) {
      const uint32_t aOff = (uint32_t)((((kk * 2 + hiA) ^ s7)) << 4);
      uint32_t a[2][4];
      ldsm4(a[0], aB + aOff);
      ldsm4(a[1], aB + 2048u + aOff);
      const uint32_t bOff = (uint32_t)((((kk * 2 + cB) ^ s7)) << 4);
      uint32_t bf[4][4];
#pragma unroll
      for (int np = 0; np < 4; np++)
        ldsm4(bf[np], bB + (uint32_t)(np * 2048) + bOff);
#pragma unroll
      for (int mt = 0; mt < 2; mt++)
#pragma unroll
        for (int np = 0; np < 4; np++) {
          mma16816(acc[mt][np * 2 + 0], a[mt], &bf[np][0]);
          mma16816(acc[mt][np * 2 + 1], a[mt], &bf[np][2]);
        }
    }
    __syncthreads();
    if (kt + 2 < KT) load_stage(kt + 2, b);
  }

  const int g = lane >> 2, t = lane & 3;
#pragma unroll
  for (int mt = 0; mt < 2; mt++) {
#pragma unroll
    for (int n8 = 0; n8 < 8; n8++) {
      const int col = nBase + wn * 64 + (n8 >> 1) * 16 + (n8 & 1) * 8 + 2 * t;
      const float d0 = __ldg(ds + col), d1 = __ldg(ds + col + 1);
      const float* cc = acc[mt][n8];
      const int r = mBase + wm * 32 + mt * 16 + g;
      *reinterpret_cast<float2*>(Out + (size_t)r * HID + col) =
          make_float2(cc[0] * d0, cc[1] * d1);
      *reinterpret_cast<float2*>(Out + (size_t)(r + 8) * HID + col) =
          make_float2(cc[2] * d0, cc[3] * d1);
    }
  }
}

// =====================================================================
extern "C" void kernel_launch(void* const* d_in, const int* in_sizes, int n_in,
                              void* d_out, int out_size) {
  const float* x      = (const float*)d_in[0];
  const float* gate_w = (const float*)d_in[1];
  const float* up_w   = (const float*)d_in[2];
  const float* down_w = (const float*)d_in[3];
  const float* gate_s = (const float*)d_in[4];
  const float* up_s   = (const float*)d_in[5];
  const float* down_s = (const float*)d_in[6];
  float* out = (float*)d_out;

  __half *xh, *wg, *wu, *wd, *hb;
  cudaGetSymbolAddress((void**)&xh, g_xh);
  cudaGetSymbolAddress((void**)&wg, g_wg);
  cudaGetSymbolAddress((void**)&wu, g_wu);
  cudaGetSymbolAddress((void**)&wd, g_wd);
  cudaGetSymbolAddress((void**)&hb, g_hbuf);

  const int SMEM = 65536;  // 2 stages x 32KB, both GEMMs
  cudaFuncSetAttribute(gemm1_mma, cudaFuncAttributeMaxDynamicSharedMemorySize, SMEM);
  cudaFuncSetAttribute(gemm2_mma, cudaFuncAttributeMaxDynamicSharedMemorySize, SMEM);

  const int n4x = (TOK * HID) / 4;
  const int n4w = (INTER * HID) / 4;
  convert_f2h<<<2048, 256>>>(x, xh, n4x);
  convert_f2h<<<2048, 256>>>(gate_w, wg, n4w);
  convert_f2h<<<2048, 256>>>(up_w, wu, n4w);
  convert_f2h<<<2048, 256>>>(down_w, wd, n4w);

  dim3 grid1(INTER / 64, TOK / 128);   // (88, 32)
  gemm1_mma<<<grid1, 256, SMEM>>>(xh, wg, wu, gate_s, up_s, hb);

  dim3 grid2(HID / 128, TOK / 128);    // (16, 32)
  gemm2_mma<<<grid2, 256, SMEM>>>(hb, wd, down_s, out);
}